// round 2
// baseline (speedup 1.0000x reference)
#include <cuda_runtime.h>
#include <cstdint>
#include <cstddef>

#define HID   256
#define NOBJ  64
#define BATCH 64
#define PITCH 264   // floats; (8*row+col)%32 is a permutation -> conflict-free LDS

// ---------------- scratch (static device globals; no runtime alloc) ----------------
__device__ float g_U[BATCH * NOBJ * HID];        // 4 MB: xf @ W1[0:26]
__device__ float g_VQ[BATCH * NOBJ * HID];       // 4 MB: xf @ W1[26:52] + qst @ W1[52:180] + b1
__device__ float g_Wt[3 * HID * HID];            // tf32-rounded copies of g2_w, g3_w, g4_w
__device__ float g_partial[BATCH * NOBJ * HID];  // per-tile column sums

__device__ __forceinline__ float f2tf32(float x) {
    uint32_t u;
    asm("cvt.rna.tf32.f32 %0, %1;" : "=r"(u) : "f"(x));
    return __uint_as_float(u);
}
__device__ __forceinline__ uint32_t fasu(float x) { return __float_as_uint(x); }

// ---------------- kernel: round g2/g3/g4 weights to tf32 once ----------------
__global__ __launch_bounds__(256) void k_wt(const float* __restrict__ w2,
                                            const float* __restrict__ w3,
                                            const float* __restrict__ w4) {
    int mat = blockIdx.x >> 8;                       // 768 blocks: 256 per matrix
    int off = ((blockIdx.x & 255) << 8) + threadIdx.x;
    const float* src = (mat == 0) ? w2 : (mat == 1) ? w3 : w4;
    g_Wt[mat * (HID * HID) + off] = f2tf32(src[off]);
}

// ---------------- kernel 1: object features + first-layer projections ----------------
// U[b,j,h]  = sum_c xf[b,j,c] * W1[c,h]          (c in [0,26))
// VQ[b,i,h] = sum_c xf[b,i,c] * W1[26+c,h] + sum_q qst[b,q]*W1[52+q,h] + b1[h]
__global__ __launch_bounds__(256) void k1(const float* __restrict__ x,
                                          const float* __restrict__ qst,
                                          const float* __restrict__ w1,
                                          const float* __restrict__ b1) {
    __shared__ float xfs[NOBJ][26];
    __shared__ float qs[128];
    int b = blockIdx.x, tid = threadIdx.x, h = tid;

    for (int idx = tid; idx < NOBJ * 26; idx += 256) {
        int j = idx / 26, c = idx % 26;
        float v;
        if (c < 24)       v = x[((size_t)b * 24 + c) * 64 + j];
        else if (c == 24) v = ((float)j * 0.125f - 4.0f) * 0.25f;   // (a/d - d/2)/(d/2)
        else              v = ((float)(j & 7) - 4.0f) * 0.25f;       // (a%d - d/2)/(d/2)
        xfs[j][c] = v;
    }
    if (tid < 128) qs[tid] = qst[b * 128 + tid];
    __syncthreads();

    float wa[26], wb[26];
#pragma unroll
    for (int c = 0; c < 26; c++) {
        wa[c] = w1[c * HID + h];
        wb[c] = w1[(26 + c) * HID + h];
    }
    float qp = b1[h];
#pragma unroll 8
    for (int q = 0; q < 128; q++) qp += qs[q] * w1[(52 + q) * HID + h];

    for (int j = 0; j < NOBJ; j++) {
        float u = 0.f, v = 0.f;
#pragma unroll
        for (int c = 0; c < 26; c++) {
            u += xfs[j][c] * wa[c];
            v += xfs[j][c] * wb[c];
        }
        g_U[((size_t)b * NOBJ + j) * HID + h]  = u;
        g_VQ[((size_t)b * NOBJ + j) * HID + h] = v + qp;
    }
}

// ---------------- kernel 2: fused g2->g3->g4 + pair-sum ----------------
// CTA = (b, i). 64 rows (all j). tf32 mma.sync m16n8k8, fp32 accumulate.
// 8 warps: warp = wm (m-tile of 16 rows, wm in 0..3) x wn (128-col half).
__device__ __forceinline__ void cp16(uint32_t dst, const float* src) {
    asm volatile("cp.async.cg.shared.global [%0], [%1], 16;" :: "r"(dst), "l"(src) : "memory");
}

__global__ __launch_bounds__(256, 1) void k2(const float* __restrict__ gb2,
                                             const float* __restrict__ gb3,
                                             const float* __restrict__ gb4) {
    extern __shared__ float sm[];
    float* Abuf0 = sm;                                   // 64 x PITCH
    float* Abuf1 = sm + 64 * PITCH;                      // 64 x PITCH
    float* WS0   = sm + 2 * 64 * PITCH;                  // 32 x PITCH
    float* WS1   = WS0 + 32 * PITCH;                     // 32 x PITCH
    float* wsum  = WS1 + 32 * PITCH;                     // 8 x 256 per-warp column sums

    const int b    = blockIdx.x >> 6;
    const int ti   = blockIdx.x & 63;                    // = i
    const int tid  = threadIdx.x;
    const int lane = tid & 31, warp = tid >> 5;
    const int wm = warp & 3, wn = warp >> 2;
    const int g = lane >> 2, t4 = lane & 3;

    // build h1 tile: rows j = 0..63, col h = tid
    {
        const float* Ub  = g_U + ((size_t)b * NOBJ) * HID;
        const float  vq  = g_VQ[((size_t)b * NOBJ + ti) * HID + tid];
#pragma unroll 8
        for (int j = 0; j < 64; j++)
            Abuf0[j * PITCH + tid] = f2tf32(fmaxf(Ub[j * HID + tid] + vq, 0.f));
    }
    for (int i = tid; i < 8 * HID; i += 256) wsum[i] = 0.f;

    float* Acur = Abuf0;
    float* Anext = Abuf1;
    uint32_t wsbase[2] = { (uint32_t)__cvta_generic_to_shared(WS0),
                           (uint32_t)__cvta_generic_to_shared(WS1) };
    float* WSp[2] = { WS0, WS1 };

#pragma unroll 1
    for (int l = 0; l < 3; l++) {
        const float* W    = g_Wt + l * (HID * HID);
        const float* bias = (l == 0) ? gb2 : (l == 1) ? gb3 : gb4;

        float acc[16][4];
#pragma unroll
        for (int a = 0; a < 16; a++) { acc[a][0] = 0.f; acc[a][1] = 0.f; acc[a][2] = 0.f; acc[a][3] = 0.f; }

        // prefetch K-chunk 0 (32 rows of W)
#pragma unroll
        for (int t = 0; t < 8; t++) {
            int lin = tid + t * 256, kr = lin >> 6, c4 = lin & 63;
            cp16(wsbase[0] + (uint32_t)((kr * PITCH + c4 * 4) * 4), W + kr * 256 + c4 * 4);
        }
        asm volatile("cp.async.commit_group;" ::: "memory");

#pragma unroll 1
        for (int kc = 0; kc < 8; kc++) {
            if (kc < 7) {
                const float* Wn = W + (kc + 1) * 32 * 256;
                uint32_t base = wsbase[(kc + 1) & 1];
#pragma unroll
                for (int t = 0; t < 8; t++) {
                    int lin = tid + t * 256, kr = lin >> 6, c4 = lin & 63;
                    cp16(base + (uint32_t)((kr * PITCH + c4 * 4) * 4), Wn + kr * 256 + c4 * 4);
                }
                asm volatile("cp.async.commit_group;" ::: "memory");
                asm volatile("cp.async.wait_group 1;" ::: "memory");
            } else {
                asm volatile("cp.async.wait_group 0;" ::: "memory");
            }
            __syncthreads();   // chunk kc visible to all threads (also covers A-build at l=0,kc=0)

            const float* WS    = WSp[kc & 1];
            const float* Abase = Acur + (wm * 16) * PITCH + kc * 32;
#pragma unroll
            for (int ks = 0; ks < 4; ks++) {
                const float* Ak = Abase + ks * 8 + t4;
                uint32_t a0 = fasu(Ak[g * PITCH]);
                uint32_t a1 = fasu(Ak[(g + 8) * PITCH]);
                uint32_t a2 = fasu(Ak[g * PITCH + 4]);
                uint32_t a3 = fasu(Ak[(g + 8) * PITCH + 4]);
                const float* Bk = WS + (ks * 8 + t4) * PITCH + wn * 128 + g;
#pragma unroll
                for (int nt = 0; nt < 16; nt++) {
                    uint32_t b0 = fasu(Bk[nt * 8]);
                    uint32_t b1 = fasu(Bk[4 * PITCH + nt * 8]);
                    asm volatile(
                        "mma.sync.aligned.m16n8k8.row.col.f32.tf32.tf32.f32 "
                        "{%0,%1,%2,%3}, {%4,%5,%6,%7}, {%8,%9}, {%0,%1,%2,%3};"
                        : "+f"(acc[nt][0]), "+f"(acc[nt][1]), "+f"(acc[nt][2]), "+f"(acc[nt][3])
                        : "r"(a0), "r"(a1), "r"(a2), "r"(a3), "r"(b0), "r"(b1));
                }
            }
            __syncthreads();   // all reads of WS[kc&1] done -> safe to overwrite at kc+2
        }

        if (l < 2) {
            // epilogue: relu(acc + bias) -> Anext (tf32-rounded)
            float* dst = Anext + (wm * 16) * PITCH + wn * 128;
#pragma unroll
            for (int nt = 0; nt < 16; nt++) {
                int c0 = nt * 8 + 2 * t4;
                float bz0 = __ldg(&bias[wn * 128 + c0]);
                float bz1 = __ldg(&bias[wn * 128 + c0 + 1]);
                dst[g * PITCH + c0]           = f2tf32(fmaxf(acc[nt][0] + bz0, 0.f));
                dst[g * PITCH + c0 + 1]       = f2tf32(fmaxf(acc[nt][1] + bz1, 0.f));
                dst[(g + 8) * PITCH + c0]     = f2tf32(fmaxf(acc[nt][2] + bz0, 0.f));
                dst[(g + 8) * PITCH + c0 + 1] = f2tf32(fmaxf(acc[nt][3] + bz1, 0.f));
            }
            __syncthreads();
            float* tmp = Acur; Acur = Anext; Anext = tmp;
        } else {
            // final layer: relu then deterministic column reduction over the 16 rows
#pragma unroll
            for (int nt = 0; nt < 16; nt++) {
                int c0 = nt * 8 + 2 * t4;
                float bz0 = __ldg(&bias[wn * 128 + c0]);
                float bz1 = __ldg(&bias[wn * 128 + c0 + 1]);
                float r0 = fmaxf(acc[nt][0] + bz0, 0.f) + fmaxf(acc[nt][2] + bz0, 0.f);
                float r1 = fmaxf(acc[nt][1] + bz1, 0.f) + fmaxf(acc[nt][3] + bz1, 0.f);
                r0 += __shfl_xor_sync(0xffffffffu, r0, 4);
                r0 += __shfl_xor_sync(0xffffffffu, r0, 8);
                r0 += __shfl_xor_sync(0xffffffffu, r0, 16);
                r1 += __shfl_xor_sync(0xffffffffu, r1, 4);
                r1 += __shfl_xor_sync(0xffffffffu, r1, 8);
                r1 += __shfl_xor_sync(0xffffffffu, r1, 16);
                if (g == 0) {   // lanes 0..3: distinct columns, per-warp region -> race-free
                    wsum[warp * HID + wn * 128 + c0]     += r0;
                    wsum[warp * HID + wn * 128 + c0 + 1] += r1;
                }
            }
        }
    }

    __syncthreads();
    float s = 0.f;
#pragma unroll
    for (int w = 0; w < 8; w++) s += wsum[w * HID + tid];
    g_partial[(size_t)blockIdx.x * HID + tid] = s;
}

// ---------------- kernel 3: tile reduction + f-MLP + log_softmax ----------------
__global__ __launch_bounds__(256) void k3(const float* __restrict__ f1w, const float* __restrict__ f1b,
                                          const float* __restrict__ f2w, const float* __restrict__ f2b,
                                          const float* __restrict__ f3w, const float* __restrict__ f3b,
                                          float* __restrict__ out) {
    __shared__ float xg[HID], y1[HID], y2[HID], lg[32];
    int b = blockIdx.x, tid = threadIdx.x;

    float s = 0.f;
#pragma unroll 8
    for (int t = 0; t < 64; t++) s += g_partial[((size_t)b * 64 + t) * HID + tid];
    xg[tid] = s;
    __syncthreads();

    float v = f1b[tid];
#pragma unroll 8
    for (int k = 0; k < HID; k++) v += xg[k] * f1w[k * HID + tid];
    y1[tid] = fmaxf(v, 0.f);
    __syncthreads();

    v = f2b[tid];
#pragma unroll 8
    for (int k = 0; k < HID; k++) v += y1[k] * f2w[k * HID + tid];
    y2[tid] = fmaxf(v, 0.f);
    __syncthreads();

    if (tid < 28) {
        v = f3b[tid];
#pragma unroll 8
        for (int k = 0; k < HID; k++) v += y2[k] * f3w[k * 28 + tid];
        lg[tid] = v;
    }
    __syncthreads();

    if (tid < 32) {
        float z = (tid < 28) ? lg[tid] : -1e30f;
        float m = z;
#pragma unroll
        for (int o = 16; o > 0; o >>= 1) m = fmaxf(m, __shfl_xor_sync(0xffffffffu, m, o));
        float e = (tid < 28) ? expf(z - m) : 0.f;
        float se = e;
#pragma unroll
        for (int o = 16; o > 0; o >>= 1) se += __shfl_xor_sync(0xffffffffu, se, o);
        if (tid < 28) out[b * 28 + tid] = z - m - logf(se);
    }
}

// ---------------- launch ----------------
extern "C" void kernel_launch(void* const* d_in, const int* in_sizes, int n_in,
                              void* d_out, int out_size) {
    (void)in_sizes; (void)n_in; (void)out_size;
    const float* x   = (const float*)d_in[0];
    const float* qst = (const float*)d_in[1];
    const float* g1w = (const float*)d_in[2];
    const float* g1b = (const float*)d_in[3];
    const float* g2w = (const float*)d_in[4];
    const float* g2b = (const float*)d_in[5];
    const float* g3w = (const float*)d_in[6];
    const float* g3b = (const float*)d_in[7];
    const float* g4w = (const float*)d_in[8];
    const float* g4b = (const float*)d_in[9];
    const float* f1w = (const float*)d_in[10];
    const float* f1b = (const float*)d_in[11];
    const float* f2w = (const float*)d_in[12];
    const float* f2b = (const float*)d_in[13];
    const float* f3w = (const float*)d_in[14];
    const float* f3b = (const float*)d_in[15];
    float* out = (float*)d_out;

    size_t smem = (size_t)(2 * 64 * PITCH + 2 * 32 * PITCH + 8 * HID) * sizeof(float); // 210944 B
    cudaFuncSetAttribute((const void*)k2, cudaFuncAttributeMaxDynamicSharedMemorySize, (int)smem);

    k_wt<<<768, 256>>>(g2w, g3w, g4w);
    k1<<<64, 256>>>(x, qst, g1w, g1b);
    k2<<<BATCH * NOBJ, 256, smem>>>(g2b, g3b, g4b);
    k3<<<BATCH, 256>>>(f1w, f1b, f2w, f2b, f3w, f3b, out);
}

// round 4
// speedup vs baseline: 2.8748x; 2.8748x over previous
#include <cuda_runtime.h>
#include <cuda_fp16.h>
#include <cstdint>
#include <cstddef>

#define HID   256
#define NOBJ  64
#define BATCH 64
#define NCTA2 2048          // 64 b x 32 i-pairs

// ---------------- static device scratch ----------------
__device__ float g_U[BATCH * NOBJ * HID];    // xf @ W1[0:26]
__device__ float g_VQ[BATCH * NOBJ * HID];   // xf @ W1[26:52] + qst @ W1[52:180] + b1
__device__ uint4 g_Bh4[3 * 4 * 2048];        // 3 layers x 4 K-chunks x 32KB fragment-packed fp16 B
__device__ float g_partial[NCTA2 * HID];

// ---------------- helpers ----------------
__device__ __forceinline__ void cp16(uint32_t dst, const void* src) {
    asm volatile("cp.async.cg.shared.global [%0], [%1], 16;" :: "r"(dst), "l"(src) : "memory");
}
__device__ __forceinline__ void cp_commit() { asm volatile("cp.async.commit_group;" ::: "memory"); }
__device__ __forceinline__ void cp_wait1()  { asm volatile("cp.async.wait_group 1;" ::: "memory"); }
__device__ __forceinline__ void cp_wait0()  { asm volatile("cp.async.wait_group 0;" ::: "memory"); }

__device__ __forceinline__ void mma16816(float acc[4], uint32_t a0, uint32_t a1, uint32_t a2, uint32_t a3,
                                         uint32_t b0, uint32_t b1) {
    asm volatile("mma.sync.aligned.m16n8k16.row.col.f32.f16.f16.f32 "
                 "{%0,%1,%2,%3}, {%4,%5,%6,%7}, {%8,%9}, {%0,%1,%2,%3};"
                 : "+f"(acc[0]), "+f"(acc[1]), "+f"(acc[2]), "+f"(acc[3])
                 : "r"(a0), "r"(a1), "r"(a2), "r"(a3), "r"(b0), "r"(b1));
}
__device__ __forceinline__ uint32_t pack2(__half lo, __half hi) {
    return (uint32_t)__half_as_ushort(lo) | ((uint32_t)__half_as_ushort(hi) << 16);
}

// ---------------- k_wt: pack g2/g3/g4 weights into per-lane fp16 fragment images ----------------
// Entry e = [wn(2)][ks(4)][npair(8)][lane(32)] of 16B, per (layer, kchunk).
// Lane(g=lane>>2,t4=lane&3): {B[k0][n0],B[k0+1][n0],B[k0+8][n0],B[k0+9][n0], same for n1=n0+8}
// with k0 = ks*16+2*t4 (chunk-local), n0 = wn*128 + npair*16 + g.
__global__ __launch_bounds__(256) void k_wt(const float* __restrict__ w2,
                                            const float* __restrict__ w3,
                                            const float* __restrict__ w4) {
    __shared__ __half sh[64 * 256];
    int l = blockIdx.x >> 2, kc = blockIdx.x & 3;
    const float* src = (l == 0) ? w2 : (l == 1) ? w3 : w4;
    int tid = threadIdx.x;
#pragma unroll 8
    for (int p = 0; p < 64; p++) {
        int idx = tid + p * 256;
        sh[idx] = __float2half_rn(src[kc * 64 * 256 + idx]);
    }
    __syncthreads();
    uint4* dst = g_Bh4 + (l * 4 + kc) * 2048;
#pragma unroll
    for (int e0 = 0; e0 < 8; e0++) {
        int e = e0 * 256 + tid;
        int lane = e & 31, npair = (e >> 5) & 7, ks = (e >> 8) & 3, wn = e >> 10;
        int g = lane >> 2, t4 = lane & 3;
        int k0 = ks * 16 + 2 * t4;
        int n0 = wn * 128 + npair * 16 + g;
        uint4 v;
        v.x = pack2(sh[k0 * 256 + n0],       sh[(k0 + 1) * 256 + n0]);
        v.y = pack2(sh[(k0 + 8) * 256 + n0], sh[(k0 + 9) * 256 + n0]);
        v.z = pack2(sh[k0 * 256 + n0 + 8],       sh[(k0 + 1) * 256 + n0 + 8]);
        v.w = pack2(sh[(k0 + 8) * 256 + n0 + 8], sh[(k0 + 9) * 256 + n0 + 8]);
        dst[e] = v;
    }
}

// ---------------- k1: first-layer projections ----------------
__global__ __launch_bounds__(256) void k1(const float* __restrict__ x,
                                          const float* __restrict__ qst,
                                          const float* __restrict__ w1,
                                          const float* __restrict__ b1) {
    __shared__ float xfs[NOBJ][26];
    __shared__ float qs[128];
    int b = blockIdx.x, tid = threadIdx.x, h = tid;

    for (int idx = tid; idx < NOBJ * 26; idx += 256) {
        int j = idx / 26, c = idx % 26;
        float v;
        if (c < 24)       v = x[((size_t)b * 24 + c) * 64 + j];
        else if (c == 24) v = ((float)j * 0.125f - 4.0f) * 0.25f;
        else              v = ((float)(j & 7) - 4.0f) * 0.25f;
        xfs[j][c] = v;
    }
    if (tid < 128) qs[tid] = qst[b * 128 + tid];
    __syncthreads();

    float wa[26], wb[26];
#pragma unroll
    for (int c = 0; c < 26; c++) {
        wa[c] = w1[c * HID + h];
        wb[c] = w1[(26 + c) * HID + h];
    }
    float q0 = b1[h], q1 = 0.f, q2 = 0.f, q3 = 0.f;
#pragma unroll 8
    for (int q = 0; q < 128; q += 4) {
        q0 += qs[q]     * w1[(52 + q)     * HID + h];
        q1 += qs[q + 1] * w1[(52 + q + 1) * HID + h];
        q2 += qs[q + 2] * w1[(52 + q + 2) * HID + h];
        q3 += qs[q + 3] * w1[(52 + q + 3) * HID + h];
    }
    float qp = (q0 + q1) + (q2 + q3);

    for (int j = 0; j < NOBJ; j++) {
        float u = 0.f, v = 0.f;
#pragma unroll
        for (int c = 0; c < 26; c++) {
            u += xfs[j][c] * wa[c];
            v += xfs[j][c] * wb[c];
        }
        g_U[((size_t)b * NOBJ + j) * HID + h]  = u;
        g_VQ[((size_t)b * NOBJ + j) * HID + h] = v + qp;
    }
}

// ---------------- k2: fused g2->g3->g4 + pair-sum (fp16 mma, fragment-order smem) ----------------
// CTA = (b, i-pair): M=128 rows (i0 rows 0..63 = j, i0+1 rows 64..127), N=256, K=256, 3 layers.
// A smem layout: [kc(4)][ks(4)][wm(4)][mt(2)][lane(32)] x 16B = 64KB (fragment images).
// B smem: 2 x 32KB double-buffered chunks streamed via cp.async from g_Bh4.
#define A_SZ     65536u
#define B_OFF    65536u
#define WSUM_OFF 131072u
#define BIAS_OFF 135168u
#define K2_SMEM  139264u

__global__ __launch_bounds__(256, 1) void k2(const float* __restrict__ gb2,
                                             const float* __restrict__ gb3,
                                             const float* __restrict__ gb4) {
    extern __shared__ unsigned char sm[];
    unsigned char* Asm = sm;
    unsigned char* Bsm = sm + B_OFF;
    float* wsum  = (float*)(sm + WSUM_OFF);   // [8][128]
    float* biasS = (float*)(sm + BIAS_OFF);   // [3][256]
    const uint32_t sB = (uint32_t)__cvta_generic_to_shared(Bsm);

    const int tid = threadIdx.x, lane = tid & 31, warp = tid >> 5;
    const int wn = warp & 1, wm = warp >> 1;
    const int g = lane >> 2, t4 = lane & 3;
    const int b = blockIdx.x >> 5, i0 = (blockIdx.x & 31) * 2;

    // biases
    biasS[tid] = gb2[tid]; biasS[256 + tid] = gb3[tid]; biasS[512 + tid] = gb4[tid];

    // prefetch B chunk (0,0)
    {
        const unsigned char* src = (const unsigned char*)g_Bh4;
#pragma unroll
        for (int t = 0; t < 8; t++) { int u = tid + t * 256; cp16(sB + u * 16, src + u * 16); }
        cp_commit();
    }

    // build layer-1 activations directly in fragment layout
    {
        const float* Ub = g_U  + (size_t)b * NOBJ * HID;
        const float* Vb = g_VQ + (size_t)b * NOBJ * HID;
        int kp = tid & 127, k0 = kp * 2;
        int kc = k0 >> 6, ks = (k0 >> 4) & 3, t4s = (k0 & 7) >> 1, pairsel = (k0 >> 3) & 1;
#pragma unroll 4
        for (int it = 0; it < 64; it++) {
            int row = it * 2 + (tid >> 7);
            float2 u = *(const float2*)(Ub + (row & 63) * HID + k0);
            float2 v = *(const float2*)(Vb + (i0 + (row >> 6)) * HID + k0);
            __half h0 = __float2half_rn(fmaxf(u.x + v.x, 0.f));
            __half h1 = __float2half_rn(fmaxf(u.y + v.y, 0.f));
            int wms = row >> 5, within = row & 31;
            int mts = (within >> 4) & 1, g8 = (within >> 3) & 1, gs = within & 7;
            int lanes = gs * 4 + t4s;
            uint32_t off = (uint32_t)(((((kc * 4 + ks) * 4 + wms) * 2 + mts) * 32 + lanes) * 16
                                      + pairsel * 8 + g8 * 4);
            *(uint32_t*)(Asm + off) = pack2(h0, h1);
        }
    }

#pragma unroll 1
    for (int l = 0; l < 3; l++) {
        float acc[2][16][4];
#pragma unroll
        for (int mt = 0; mt < 2; mt++)
#pragma unroll
            for (int nt = 0; nt < 16; nt++) {
                acc[mt][nt][0] = 0.f; acc[mt][nt][1] = 0.f; acc[mt][nt][2] = 0.f; acc[mt][nt][3] = 0.f;
            }

#pragma unroll 1
        for (int kc = 0; kc < 4; kc++) {
            if (kc < 3) {
                const unsigned char* src = (const unsigned char*)g_Bh4 + (size_t)(l * 4 + kc + 1) * 32768;
                uint32_t base = sB + (uint32_t)(((kc + 1) & 1) * 32768);
#pragma unroll
                for (int t = 0; t < 8; t++) { int u = tid + t * 256; cp16(base + u * 16, src + u * 16); }
                cp_commit();
                cp_wait1();
            } else {
                cp_wait0();
            }
            __syncthreads();

            const unsigned char* Bb = Bsm + (kc & 1) * 32768;
            const unsigned char* Ab = Asm;
#pragma unroll
            for (int ks = 0; ks < 4; ks++) {
                uint32_t bb[8][4];
#pragma unroll
                for (int np = 0; np < 8; np++) {
                    uint4 v = *(const uint4*)(Bb + (size_t)((((wn * 4 + ks) * 8 + np) * 32 + lane) * 16));
                    bb[np][0] = v.x; bb[np][1] = v.y; bb[np][2] = v.z; bb[np][3] = v.w;
                }
#pragma unroll
                for (int mt = 0; mt < 2; mt++) {
                    uint4 a = *(const uint4*)(Ab + (size_t)((((((kc * 4 + ks) * 4 + wm) * 2 + mt) * 32) + lane) * 16));
#pragma unroll
                    for (int nt = 0; nt < 16; nt++) {
                        int np = nt >> 1, s = (nt & 1) * 2;
                        mma16816(acc[mt][nt], a.x, a.y, a.z, a.w, bb[np][s], bb[np][s + 1]);
                    }
                }
            }
            __syncthreads();   // all reads of buf kc&1 and (at kc=3) of A done
        }

        if (l < 2) {
            // prefetch next layer chunk 0 (buf0 free)
            const unsigned char* src = (const unsigned char*)g_Bh4 + (size_t)((l + 1) * 4) * 32768;
#pragma unroll
            for (int t = 0; t < 8; t++) { int u = tid + t * 256; cp16(sB + u * 16, src + u * 16); }
            cp_commit();

            // epilogue: relu(acc+bias) -> A (fragment layout, in place)
            const float* bias = biasS + l * 256;
#pragma unroll
            for (int mt = 0; mt < 2; mt++)
#pragma unroll
                for (int nt = 0; nt < 16; nt++) {
                    int c0 = wn * 128 + nt * 8 + 2 * t4;
                    float bz0 = bias[c0], bz1 = bias[c0 + 1];
                    __half2 hg  = __halves2half2(__float2half_rn(fmaxf(acc[mt][nt][0] + bz0, 0.f)),
                                                 __float2half_rn(fmaxf(acc[mt][nt][1] + bz1, 0.f)));
                    __half2 hg8 = __halves2half2(__float2half_rn(fmaxf(acc[mt][nt][2] + bz0, 0.f)),
                                                 __float2half_rn(fmaxf(acc[mt][nt][3] + bz1, 0.f)));
                    int kcn = c0 >> 6, ksn = (c0 >> 4) & 3, pairsel = (c0 >> 3) & 1;
                    uint32_t off = (uint32_t)(((((kcn * 4 + ksn) * 4 + wm) * 2 + mt) * 32 + lane) * 16 + pairsel * 8);
                    uint2 st; st.x = *(uint32_t*)&hg; st.y = *(uint32_t*)&hg8;
                    *(uint2*)(Asm + off) = st;
                }
            __syncthreads();
        } else {
            // final layer: relu + deterministic column reduction
            const float* bias = biasS + 512;
#pragma unroll
            for (int nt = 0; nt < 16; nt++) {
                int c0 = wn * 128 + nt * 8 + 2 * t4;
                float bz0 = bias[c0], bz1 = bias[c0 + 1];
                float s0 = fmaxf(acc[0][nt][0] + bz0, 0.f) + fmaxf(acc[0][nt][2] + bz0, 0.f)
                         + fmaxf(acc[1][nt][0] + bz0, 0.f) + fmaxf(acc[1][nt][2] + bz0, 0.f);
                float s1 = fmaxf(acc[0][nt][1] + bz1, 0.f) + fmaxf(acc[0][nt][3] + bz1, 0.f)
                         + fmaxf(acc[1][nt][1] + bz1, 0.f) + fmaxf(acc[1][nt][3] + bz1, 0.f);
                s0 += __shfl_xor_sync(0xffffffffu, s0, 4);
                s0 += __shfl_xor_sync(0xffffffffu, s0, 8);
                s0 += __shfl_xor_sync(0xffffffffu, s0, 16);
                s1 += __shfl_xor_sync(0xffffffffu, s1, 4);
                s1 += __shfl_xor_sync(0xffffffffu, s1, 8);
                s1 += __shfl_xor_sync(0xffffffffu, s1, 16);
                if (g == 0) {
                    wsum[warp * 128 + nt * 8 + 2 * t4]     = s0;
                    wsum[warp * 128 + nt * 8 + 2 * t4 + 1] = s1;
                }
            }
            __syncthreads();
            int wnc = tid >> 7, cl = tid & 127;
            float s = wsum[(0 * 2 + wnc) * 128 + cl] + wsum[(1 * 2 + wnc) * 128 + cl]
                    + wsum[(2 * 2 + wnc) * 128 + cl] + wsum[(3 * 2 + wnc) * 128 + cl];
            g_partial[(size_t)blockIdx.x * HID + tid] = s;
        }
    }
}

// ---------------- k3: tile reduction + f-MLP + log_softmax ----------------
__global__ __launch_bounds__(256) void k3(const float* __restrict__ f1w, const float* __restrict__ f1b,
                                          const float* __restrict__ f2w, const float* __restrict__ f2b,
                                          const float* __restrict__ f3w, const float* __restrict__ f3b,
                                          float* __restrict__ out) {
    __shared__ float xg[HID], y1[HID], y2[HID], lg[32];
    int b = blockIdx.x, tid = threadIdx.x;

    float s = 0.f;
#pragma unroll
    for (int t = 0; t < 32; t++) s += g_partial[((size_t)b * 32 + t) * HID + tid];
    xg[tid] = s;
    __syncthreads();

    {
        float a0 = f1b[tid], a1 = 0.f, a2 = 0.f, a3 = 0.f;
#pragma unroll 8
        for (int k = 0; k < HID; k += 4) {
            a0 += xg[k]     * f1w[k       * HID + tid];
            a1 += xg[k + 1] * f1w[(k + 1) * HID + tid];
            a2 += xg[k + 2] * f1w[(k + 2) * HID + tid];
            a3 += xg[k + 3] * f1w[(k + 3) * HID + tid];
        }
        y1[tid] = fmaxf((a0 + a1) + (a2 + a3), 0.f);
    }
    __syncthreads();
    {
        float a0 = f2b[tid], a1 = 0.f, a2 = 0.f, a3 = 0.f;
#pragma unroll 8
        for (int k = 0; k < HID; k += 4) {
            a0 += y1[k]     * f2w[k       * HID + tid];
            a1 += y1[k + 1] * f2w[(k + 1) * HID + tid];
            a2 += y1[k + 2] * f2w[(k + 2) * HID + tid];
            a3 += y1[k + 3] * f2w[(k + 3) * HID + tid];
        }
        y2[tid] = fmaxf((a0 + a1) + (a2 + a3), 0.f);
    }
    __syncthreads();

    if (tid < 28) {
        float a0 = f3b[tid], a1 = 0.f, a2 = 0.f, a3 = 0.f;
#pragma unroll 8
        for (int k = 0; k < HID; k += 4) {
            a0 += y2[k]     * f3w[k       * 28 + tid];
            a1 += y2[k + 1] * f3w[(k + 1) * 28 + tid];
            a2 += y2[k + 2] * f3w[(k + 2) * 28 + tid];
            a3 += y2[k + 3] * f3w[(k + 3) * 28 + tid];
        }
        lg[tid] = (a0 + a1) + (a2 + a3);
    }
    __syncthreads();

    if (tid < 32) {
        float z = (tid < 28) ? lg[tid] : -1e30f;
        float m = z;
#pragma unroll
        for (int o = 16; o > 0; o >>= 1) m = fmaxf(m, __shfl_xor_sync(0xffffffffu, m, o));
        float e = (tid < 28) ? expf(z - m) : 0.f;
        float se = e;
#pragma unroll
        for (int o = 16; o > 0; o >>= 1) se += __shfl_xor_sync(0xffffffffu, se, o);
        if (tid < 28) out[b * 28 + tid] = z - m - logf(se);
    }
}

// ---------------- launch ----------------
extern "C" void kernel_launch(void* const* d_in, const int* in_sizes, int n_in,
                              void* d_out, int out_size) {
    (void)in_sizes; (void)n_in; (void)out_size;
    const float* x   = (const float*)d_in[0];
    const float* qst = (const float*)d_in[1];
    const float* g1w = (const float*)d_in[2];
    const float* g1b = (const float*)d_in[3];
    const float* g2w = (const float*)d_in[4];
    const float* g2b = (const float*)d_in[5];
    const float* g3w = (const float*)d_in[6];
    const float* g3b = (const float*)d_in[7];
    const float* g4w = (const float*)d_in[8];
    const float* g4b = (const float*)d_in[9];
    const float* f1w = (const float*)d_in[10];
    const float* f1b = (const float*)d_in[11];
    const float* f2w = (const float*)d_in[12];
    const float* f2b = (const float*)d_in[13];
    const float* f3w = (const float*)d_in[14];
    const float* f3b = (const float*)d_in[15];
    float* out = (float*)d_out;

    cudaFuncSetAttribute((const void*)k2, cudaFuncAttributeMaxDynamicSharedMemorySize, (int)K2_SMEM);

    k_wt<<<12, 256>>>(g2w, g3w, g4w);
    k1<<<64, 256>>>(x, qst, g1w, g1b);
    k2<<<NCTA2, 256, K2_SMEM>>>(g2b, g3b, g4b);
    k3<<<64, 256>>>(f1w, f1b, f2w, f2b, f3w, f3b, out);
}

// round 5
// speedup vs baseline: 3.0562x; 1.0631x over previous
#include <cuda_runtime.h>
#include <cuda_fp16.h>
#include <cstdint>
#include <cstddef>

#define HID   256
#define NOBJ  64
#define BATCH 64
#define NCTA2 2048          // 64 b x 32 i-pairs

// ---------------- static device scratch ----------------
__device__ float g_U[BATCH * NOBJ * HID];    // xf @ W1[0:26]
__device__ float g_VQ[BATCH * NOBJ * HID];   // xf @ W1[26:52] + qst @ W1[52:180] + b1
__device__ uint4 g_Bh4[3 * 4 * 2048];        // 3 layers x 4 K-chunks x 32KB fragment-packed fp16 B
__device__ float g_partial[NCTA2 * HID];

// ---------------- helpers ----------------
__device__ __forceinline__ void cp16(uint32_t dst, const void* src) {
    asm volatile("cp.async.cg.shared.global [%0], [%1], 16;" :: "r"(dst), "l"(src) : "memory");
}
__device__ __forceinline__ void cp_commit() { asm volatile("cp.async.commit_group;" ::: "memory"); }
__device__ __forceinline__ void cp_wait0()  { asm volatile("cp.async.wait_group 0;" ::: "memory"); }

__device__ __forceinline__ void mma16816(float acc[4], uint32_t a0, uint32_t a1, uint32_t a2, uint32_t a3,
                                         uint32_t b0, uint32_t b1) {
    asm volatile("mma.sync.aligned.m16n8k16.row.col.f32.f16.f16.f32 "
                 "{%0,%1,%2,%3}, {%4,%5,%6,%7}, {%8,%9}, {%0,%1,%2,%3};"
                 : "+f"(acc[0]), "+f"(acc[1]), "+f"(acc[2]), "+f"(acc[3])
                 : "r"(a0), "r"(a1), "r"(a2), "r"(a3), "r"(b0), "r"(b1));
}
__device__ __forceinline__ uint32_t pack2(__half lo, __half hi) {
    return (uint32_t)__half_as_ushort(lo) | ((uint32_t)__half_as_ushort(hi) << 16);
}

// ---------------- k0: merged weight-pack (blocks 0..11) + first-layer projections (blocks 12..75) ----------------
__global__ __launch_bounds__(256) void k0(const float* __restrict__ x,
                                          const float* __restrict__ qst,
                                          const float* __restrict__ w1,
                                          const float* __restrict__ b1,
                                          const float* __restrict__ w2,
                                          const float* __restrict__ w3,
                                          const float* __restrict__ w4) {
    __shared__ __align__(16) unsigned char sraw[64 * 256 * 2];   // 32KB
    int bx = blockIdx.x, tid = threadIdx.x;

    if (bx < 12) {
        // ---- weight pack: per-lane fp16 fragment images ----
        __half* sh = (__half*)sraw;
        int l = bx >> 2, kc = bx & 3;
        const float* src = (l == 0) ? w2 : (l == 1) ? w3 : w4;
#pragma unroll 8
        for (int p = 0; p < 64; p++) {
            int idx = tid + p * 256;
            sh[idx] = __float2half_rn(src[kc * 64 * 256 + idx]);
        }
        __syncthreads();
        uint4* dst = g_Bh4 + (l * 4 + kc) * 2048;
#pragma unroll
        for (int e0 = 0; e0 < 8; e0++) {
            int e = e0 * 256 + tid;
            int lane = e & 31, npair = (e >> 5) & 7, ks = (e >> 8) & 3, wn = e >> 10;
            int g = lane >> 2, t4 = lane & 3;
            int k0 = ks * 16 + 2 * t4;
            int n0 = wn * 128 + npair * 16 + g;
            uint4 v;
            v.x = pack2(sh[k0 * 256 + n0],       sh[(k0 + 1) * 256 + n0]);
            v.y = pack2(sh[(k0 + 8) * 256 + n0], sh[(k0 + 9) * 256 + n0]);
            v.z = pack2(sh[k0 * 256 + n0 + 8],       sh[(k0 + 1) * 256 + n0 + 8]);
            v.w = pack2(sh[(k0 + 8) * 256 + n0 + 8], sh[(k0 + 9) * 256 + n0 + 8]);
            dst[e] = v;
        }
    } else {
        // ---- first-layer projections ----
        float* xfs = (float*)sraw;            // [64][26]
        float* qs  = xfs + NOBJ * 26;         // [128]
        int b = bx - 12, h = tid;

        for (int idx = tid; idx < NOBJ * 26; idx += 256) {
            int j = idx / 26, c = idx % 26;
            float v;
            if (c < 24)       v = x[((size_t)b * 24 + c) * 64 + j];
            else if (c == 24) v = ((float)j * 0.125f - 4.0f) * 0.25f;
            else              v = ((float)(j & 7) - 4.0f) * 0.25f;
            xfs[j * 26 + c] = v;
        }
        if (tid < 128) qs[tid] = qst[b * 128 + tid];
        __syncthreads();

        float wa[26], wb[26];
#pragma unroll
        for (int c = 0; c < 26; c++) {
            wa[c] = w1[c * HID + h];
            wb[c] = w1[(26 + c) * HID + h];
        }
        float q0 = b1[h], q1 = 0.f, q2 = 0.f, q3 = 0.f;
#pragma unroll 8
        for (int q = 0; q < 128; q += 4) {
            q0 += qs[q]     * w1[(52 + q)     * HID + h];
            q1 += qs[q + 1] * w1[(52 + q + 1) * HID + h];
            q2 += qs[q + 2] * w1[(52 + q + 2) * HID + h];
            q3 += qs[q + 3] * w1[(52 + q + 3) * HID + h];
        }
        float qp = (q0 + q1) + (q2 + q3);

        for (int j = 0; j < NOBJ; j++) {
            float u = 0.f, v = 0.f;
#pragma unroll
            for (int c = 0; c < 26; c++) {
                u += xfs[j * 26 + c] * wa[c];
                v += xfs[j * 26 + c] * wb[c];
            }
            g_U[((size_t)b * NOBJ + j) * HID + h]  = u;
            g_VQ[((size_t)b * NOBJ + j) * HID + h] = v + qp;
        }
    }
}

// ---------------- k2: fused g2->g3->g4 + pair-sum (fp16 mma, fragment-order smem) ----------------
// CTA = (b, i-pair): M=128, N=256, K=256, 3 layers. One __syncthreads per K-chunk.
// A smem: [kc(4)][ks(4)][wm(4)][mt(2)][lane(32)] x 16B = 64KB. B: 2 x 32KB double-buffered.
#define B_OFF    65536u
#define WSUM_OFF 131072u
#define BIAS_OFF 135168u
#define K2_SMEM  139264u

__global__ __launch_bounds__(256, 1) void k2(const float* __restrict__ gb2,
                                             const float* __restrict__ gb3,
                                             const float* __restrict__ gb4) {
    extern __shared__ unsigned char sm[];
    unsigned char* Asm = sm;
    unsigned char* Bsm = sm + B_OFF;
    float* wsum  = (float*)(sm + WSUM_OFF);   // [8][128]
    float* biasS = (float*)(sm + BIAS_OFF);   // [3][256]
    const uint32_t sB = (uint32_t)__cvta_generic_to_shared(Bsm);

    const int tid = threadIdx.x, lane = tid & 31, warp = tid >> 5;
    const int wn = warp & 1, wm = warp >> 1;
    const int g = lane >> 2, t4 = lane & 3;
    const int b = blockIdx.x >> 5, i0 = (blockIdx.x & 31) * 2;

    biasS[tid] = gb2[tid]; biasS[256 + tid] = gb3[tid]; biasS[512 + tid] = gb4[tid];

    // prefetch B chunk 0
    {
        const unsigned char* src = (const unsigned char*)g_Bh4;
#pragma unroll
        for (int t = 0; t < 8; t++) { int u = tid + t * 256; cp16(sB + u * 16, src + u * 16); }
        cp_commit();
    }

    // build layer-1 activations directly in fragment layout
    {
        const float* Ub = g_U  + (size_t)b * NOBJ * HID;
        const float* Vb = g_VQ + (size_t)b * NOBJ * HID;
        int kp = tid & 127, k0 = kp * 2;
        int kc = k0 >> 6, ks = (k0 >> 4) & 3, t4s = (k0 & 7) >> 1, pairsel = (k0 >> 3) & 1;
#pragma unroll 4
        for (int it = 0; it < 64; it++) {
            int row = it * 2 + (tid >> 7);
            float2 u = *(const float2*)(Ub + (row & 63) * HID + k0);
            float2 v = *(const float2*)(Vb + (i0 + (row >> 6)) * HID + k0);
            __half h0 = __float2half_rn(fmaxf(u.x + v.x, 0.f));
            __half h1 = __float2half_rn(fmaxf(u.y + v.y, 0.f));
            int wms = row >> 5, within = row & 31;
            int mts = (within >> 4) & 1, g8 = (within >> 3) & 1, gs = within & 7;
            int lanes = gs * 4 + t4s;
            uint32_t off = (uint32_t)(((((kc * 4 + ks) * 4 + wms) * 2 + mts) * 32 + lanes) * 16
                                      + pairsel * 8 + g8 * 4);
            *(uint32_t*)(Asm + off) = pack2(h0, h1);
        }
    }

#pragma unroll 1
    for (int l = 0; l < 3; l++) {
        float acc[2][16][4];
#pragma unroll
        for (int mt = 0; mt < 2; mt++)
#pragma unroll
            for (int nt = 0; nt < 16; nt++) {
                acc[mt][nt][0] = 0.f; acc[mt][nt][1] = 0.f; acc[mt][nt][2] = 0.f; acc[mt][nt][3] = 0.f;
            }

#pragma unroll 1
        for (int kc = 0; kc < 4; kc++) {
            const int c = l * 4 + kc;
            cp_wait0();          // chunk c resident (issued last iteration)
            __syncthreads();     // ...for everyone; also: all reads of buf (c+1)&1 from iter c-1 done
            if (c < 11) {        // stream chunk c+1 into the other buffer
                const unsigned char* src = (const unsigned char*)g_Bh4 + (size_t)(c + 1) * 32768;
                uint32_t base = sB + (uint32_t)(((c + 1) & 1) * 32768);
#pragma unroll
                for (int t = 0; t < 8; t++) { int u = tid + t * 256; cp16(base + u * 16, src + u * 16); }
                cp_commit();
            }

            const unsigned char* Bb = Bsm + (c & 1) * 32768;
#pragma unroll
            for (int ks = 0; ks < 4; ks++) {
                uint32_t bb[8][4];
#pragma unroll
                for (int np = 0; np < 8; np++) {
                    uint4 v = *(const uint4*)(Bb + (size_t)((((wn * 4 + ks) * 8 + np) * 32 + lane) * 16));
                    bb[np][0] = v.x; bb[np][1] = v.y; bb[np][2] = v.z; bb[np][3] = v.w;
                }
#pragma unroll
                for (int mt = 0; mt < 2; mt++) {
                    uint4 a = *(const uint4*)(Asm + (size_t)((((((kc * 4 + ks) * 4 + wm) * 2 + mt) * 32) + lane) * 16));
#pragma unroll
                    for (int nt = 0; nt < 16; nt++) {
                        int np = nt >> 1, s = (nt & 1) * 2;
                        mma16816(acc[mt][nt], a.x, a.y, a.z, a.w, bb[np][s], bb[np][s + 1]);
                    }
                }
            }
        }
        __syncthreads();   // all mma reads of A done before epilogue overwrites A

        if (l < 2) {
            const float* bias = biasS + l * 256;
#pragma unroll
            for (int mt = 0; mt < 2; mt++)
#pragma unroll
                for (int nt = 0; nt < 16; nt++) {
                    int c0 = wn * 128 + nt * 8 + 2 * t4;
                    float bz0 = bias[c0], bz1 = bias[c0 + 1];
                    __half2 hg  = __halves2half2(__float2half_rn(fmaxf(acc[mt][nt][0] + bz0, 0.f)),
                                                 __float2half_rn(fmaxf(acc[mt][nt][1] + bz1, 0.f)));
                    __half2 hg8 = __halves2half2(__float2half_rn(fmaxf(acc[mt][nt][2] + bz0, 0.f)),
                                                 __float2half_rn(fmaxf(acc[mt][nt][3] + bz1, 0.f)));
                    int kcn = c0 >> 6, ksn = (c0 >> 4) & 3, pairsel = (c0 >> 3) & 1;
                    uint32_t off = (uint32_t)(((((kcn * 4 + ksn) * 4 + wm) * 2 + mt) * 32 + lane) * 16 + pairsel * 8);
                    uint2 st; st.x = *(uint32_t*)&hg; st.y = *(uint32_t*)&hg8;
                    *(uint2*)(Asm + off) = st;
                }
            // next-layer mma reads are ordered after these writes by the sync at top of kc=0
        } else {
            const float* bias = biasS + 512;
#pragma unroll
            for (int nt = 0; nt < 16; nt++) {
                int c0 = wn * 128 + nt * 8 + 2 * t4;
                float bz0 = bias[c0], bz1 = bias[c0 + 1];
                float s0 = fmaxf(acc[0][nt][0] + bz0, 0.f) + fmaxf(acc[0][nt][2] + bz0, 0.f)
                         + fmaxf(acc[1][nt][0] + bz0, 0.f) + fmaxf(acc[1][nt][2] + bz0, 0.f);
                float s1 = fmaxf(acc[0][nt][1] + bz1, 0.f) + fmaxf(acc[0][nt][3] + bz1, 0.f)
                         + fmaxf(acc[1][nt][1] + bz1, 0.f) + fmaxf(acc[1][nt][3] + bz1, 0.f);
                s0 += __shfl_xor_sync(0xffffffffu, s0, 4);
                s0 += __shfl_xor_sync(0xffffffffu, s0, 8);
                s0 += __shfl_xor_sync(0xffffffffu, s0, 16);
                s1 += __shfl_xor_sync(0xffffffffu, s1, 4);
                s1 += __shfl_xor_sync(0xffffffffu, s1, 8);
                s1 += __shfl_xor_sync(0xffffffffu, s1, 16);
                if (g == 0) {
                    wsum[warp * 128 + nt * 8 + 2 * t4]     = s0;
                    wsum[warp * 128 + nt * 8 + 2 * t4 + 1] = s1;
                }
            }
            __syncthreads();
            int wnc = tid >> 7, cl = tid & 127;
            float s = wsum[(0 * 2 + wnc) * 128 + cl] + wsum[(1 * 2 + wnc) * 128 + cl]
                    + wsum[(2 * 2 + wnc) * 128 + cl] + wsum[(3 * 2 + wnc) * 128 + cl];
            g_partial[(size_t)blockIdx.x * HID + tid] = s;
        }
    }
}

// ---------------- k3: tile reduction + f-MLP + log_softmax (1024 threads, k-split) ----------------
__global__ __launch_bounds__(1024) void k3(const float* __restrict__ f1w, const float* __restrict__ f1b,
                                           const float* __restrict__ f2w, const float* __restrict__ f2b,
                                           const float* __restrict__ f3w, const float* __restrict__ f3b,
                                           float* __restrict__ out) {
    __shared__ float part[4 * 256];
    __shared__ float xg[HID], y1[HID], y2[HID];
    int b = blockIdx.x, tid = threadIdx.x;
    int col = tid & 255, q = tid >> 8;   // q in 0..3

    // stage 1: reduce 32 tiles, 8 per q-slice
    {
        float s = 0.f;
#pragma unroll
        for (int t = 0; t < 8; t++)
            s += g_partial[((size_t)b * 32 + q * 8 + t) * HID + col];
        part[q * 256 + col] = s;
    }
    __syncthreads();
    if (q == 0) xg[col] = (part[col] + part[256 + col]) + (part[512 + col] + part[768 + col]);
    __syncthreads();

    // f1: each q-slice handles 64 k's
    {
        const float* W = f1w + q * 64 * HID;
        const float* xk = xg + q * 64;
        float a0 = 0.f, a1 = 0.f, a2 = 0.f, a3 = 0.f;
#pragma unroll 8
        for (int k = 0; k < 64; k += 4) {
            a0 += xk[k]     * W[k       * HID + col];
            a1 += xk[k + 1] * W[(k + 1) * HID + col];
            a2 += xk[k + 2] * W[(k + 2) * HID + col];
            a3 += xk[k + 3] * W[(k + 3) * HID + col];
        }
        part[q * 256 + col] = (a0 + a1) + (a2 + a3);
    }
    __syncthreads();
    if (q == 0) y1[col] = fmaxf((part[col] + part[256 + col]) + (part[512 + col] + part[768 + col]) + f1b[col], 0.f);
    __syncthreads();

    // f2
    {
        const float* W = f2w + q * 64 * HID;
        const float* xk = y1 + q * 64;
        float a0 = 0.f, a1 = 0.f, a2 = 0.f, a3 = 0.f;
#pragma unroll 8
        for (int k = 0; k < 64; k += 4) {
            a0 += xk[k]     * W[k       * HID + col];
            a1 += xk[k + 1] * W[(k + 1) * HID + col];
            a2 += xk[k + 2] * W[(k + 2) * HID + col];
            a3 += xk[k + 3] * W[(k + 3) * HID + col];
        }
        part[q * 256 + col] = (a0 + a1) + (a2 + a3);
    }
    __syncthreads();
    if (q == 0) y2[col] = fmaxf((part[col] + part[256 + col]) + (part[512 + col] + part[768 + col]) + f2b[col], 0.f);
    __syncthreads();

    // f3: 28 outputs x 8 k-slices of 32
    if (tid < 256) {
        int o = tid & 31, q8 = tid >> 5;
        if (o < 28) {
            const float* W = f3w + q8 * 32 * 28;
            const float* xk = y2 + q8 * 32;
            float a0 = 0.f, a1 = 0.f;
#pragma unroll
            for (int k = 0; k < 32; k += 2) {
                a0 += xk[k]     * W[k       * 28 + o];
                a1 += xk[k + 1] * W[(k + 1) * 28 + o];
            }
            part[q8 * 28 + o] = a0 + a1;
        }
    }
    __syncthreads();

    if (tid < 32) {
        float z;
        if (tid < 28) {
            z = f3b[tid];
#pragma unroll
            for (int p = 0; p < 8; p++) z += part[p * 28 + tid];
        } else {
            z = -1e30f;
        }
        float m = z;
#pragma unroll
        for (int o = 16; o > 0; o >>= 1) m = fmaxf(m, __shfl_xor_sync(0xffffffffu, m, o));
        float e = (tid < 28) ? expf(z - m) : 0.f;
        float se = e;
#pragma unroll
        for (int o = 16; o > 0; o >>= 1) se += __shfl_xor_sync(0xffffffffu, se, o);
        if (tid < 28) out[b * 28 + tid] = z - m - logf(se);
    }
}

// ---------------- launch ----------------
extern "C" void kernel_launch(void* const* d_in, const int* in_sizes, int n_in,
                              void* d_out, int out_size) {
    (void)in_sizes; (void)n_in; (void)out_size;
    const float* x   = (const float*)d_in[0];
    const float* qst = (const float*)d_in[1];
    const float* g1w = (const float*)d_in[2];
    const float* g1b = (const float*)d_in[3];
    const float* g2w = (const float*)d_in[4];
    const float* g2b = (const float*)d_in[5];
    const float* g3w = (const float*)d_in[6];
    const float* g3b = (const float*)d_in[7];
    const float* g4w = (const float*)d_in[8];
    const float* g4b = (const float*)d_in[9];
    const float* f1w = (const float*)d_in[10];
    const float* f1b = (const float*)d_in[11];
    const float* f2w = (const float*)d_in[12];
    const float* f2b = (const float*)d_in[13];
    const float* f3w = (const float*)d_in[14];
    const float* f3b = (const float*)d_in[15];
    float* out = (float*)d_out;

    cudaFuncSetAttribute((const void*)k2, cudaFuncAttributeMaxDynamicSharedMemorySize, (int)K2_SMEM);

    k0<<<76, 256>>>(x, qst, g1w, g1b, g2w, g3w, g4w);
    k2<<<NCTA2, 256, K2_SMEM>>>(g2b, g3b, g4b);
    k3<<<64, 1024>>>(f1w, f1b, f2w, f2b, f3w, f3b, out);
}

// round 6
// speedup vs baseline: 3.4205x; 1.1192x over previous
#include <cuda_runtime.h>
#include <cuda_fp16.h>
#include <cstdint>
#include <cstddef>

#define HID   256
#define NOBJ  64
#define BATCH 64
#define NCTA2 2048          // 64 b x 32 i-pairs

// ---------------- static device scratch ----------------
__device__ float g_U[BATCH * NOBJ * HID];    // xf @ W1[0:26]
__device__ float g_VQ[BATCH * NOBJ * HID];   // xf @ W1[26:52] + qst @ W1[52:180] + b1
__device__ uint4 g_Bh4[3 * 4 * 2048];        // 3 layers x 4 K-chunks x 32KB fragment-packed fp16 B
__device__ float g_partial[NCTA2 * HID];

// ---------------- helpers ----------------
__device__ __forceinline__ void cp16(uint32_t dst, const void* src) {
    asm volatile("cp.async.cg.shared.global [%0], [%1], 16;" :: "r"(dst), "l"(src) : "memory");
}
__device__ __forceinline__ void cp_commit() { asm volatile("cp.async.commit_group;" ::: "memory"); }
__device__ __forceinline__ void cp_wait0()  { asm volatile("cp.async.wait_group 0;" ::: "memory"); }

__device__ __forceinline__ void mma16816(float acc[4], uint32_t a0, uint32_t a1, uint32_t a2, uint32_t a3,
                                         uint32_t b0, uint32_t b1) {
    asm volatile("mma.sync.aligned.m16n8k16.row.col.f32.f16.f16.f32 "
                 "{%0,%1,%2,%3}, {%4,%5,%6,%7}, {%8,%9}, {%0,%1,%2,%3};"
                 : "+f"(acc[0]), "+f"(acc[1]), "+f"(acc[2]), "+f"(acc[3])
                 : "r"(a0), "r"(a1), "r"(a2), "r"(a3), "r"(b0), "r"(b1));
}
__device__ __forceinline__ uint32_t pack2(__half lo, __half hi) {
    return (uint32_t)__half_as_ushort(lo) | ((uint32_t)__half_as_ushort(hi) << 16);
}

// ---------------- k0: weight-pack (blocks 0..11) + first-layer projections (blocks 12..139) ----------------
__global__ __launch_bounds__(256) void k0(const float* __restrict__ x,
                                          const float* __restrict__ qst,
                                          const float* __restrict__ w1,
                                          const float* __restrict__ b1,
                                          const float* __restrict__ w2,
                                          const float* __restrict__ w3,
                                          const float* __restrict__ w4) {
    __shared__ __align__(16) unsigned char sraw[64 * 256 * 2];   // 32KB
    int bx = blockIdx.x, tid = threadIdx.x;

    if (bx < 12) {
        // ---- weight pack: per-lane fp16 fragment images ----
        __half* sh = (__half*)sraw;
        int l = bx >> 2, kc = bx & 3;
        const float* src = (l == 0) ? w2 : (l == 1) ? w3 : w4;
#pragma unroll 8
        for (int p = 0; p < 64; p++) {
            int idx = tid + p * 256;
            sh[idx] = __float2half_rn(src[kc * 64 * 256 + idx]);
        }
        __syncthreads();
        uint4* dst = g_Bh4 + (l * 4 + kc) * 2048;
#pragma unroll
        for (int e0 = 0; e0 < 8; e0++) {
            int e = e0 * 256 + tid;
            int lane = e & 31, npair = (e >> 5) & 7, ks = (e >> 8) & 3, wn = e >> 10;
            int g = lane >> 2, t4 = lane & 3;
            int k0 = ks * 16 + 2 * t4;
            int n0 = wn * 128 + npair * 16 + g;
            uint4 v;
            v.x = pack2(sh[k0 * 256 + n0],       sh[(k0 + 1) * 256 + n0]);
            v.y = pack2(sh[(k0 + 8) * 256 + n0], sh[(k0 + 9) * 256 + n0]);
            v.z = pack2(sh[k0 * 256 + n0 + 8],       sh[(k0 + 1) * 256 + n0 + 8]);
            v.w = pack2(sh[(k0 + 8) * 256 + n0 + 8], sh[(k0 + 9) * 256 + n0 + 8]);
            dst[e] = v;
        }
    } else {
        // ---- first-layer projections: 2 CTAs per batch, 32 j-rows each ----
        float* xfs = (float*)sraw;            // [32][26]
        float* qs  = xfs + 32 * 26;           // [128]
        int bb = bx - 12;
        int b = bb >> 1, j0 = (bb & 1) * 32;
        int h = tid;

        for (int idx = tid; idx < 32 * 26; idx += 256) {
            int jl = idx / 26, c = idx % 26;
            int j = j0 + jl;
            float v;
            if (c < 24)       v = x[((size_t)b * 24 + c) * 64 + j];
            else if (c == 24) v = ((float)j * 0.125f - 4.0f) * 0.25f;
            else              v = ((float)(j & 7) - 4.0f) * 0.25f;
            xfs[jl * 26 + c] = v;
        }
        if (tid < 128) qs[tid] = qst[b * 128 + tid];
        __syncthreads();

        float wa[26], wb[26];
#pragma unroll
        for (int c = 0; c < 26; c++) {
            wa[c] = w1[c * HID + h];
            wb[c] = w1[(26 + c) * HID + h];
        }
        float q0 = b1[h], q1 = 0.f, q2 = 0.f, q3 = 0.f;
#pragma unroll 8
        for (int q = 0; q < 128; q += 4) {
            q0 += qs[q]     * w1[(52 + q)     * HID + h];
            q1 += qs[q + 1] * w1[(52 + q + 1) * HID + h];
            q2 += qs[q + 2] * w1[(52 + q + 2) * HID + h];
            q3 += qs[q + 3] * w1[(52 + q + 3) * HID + h];
        }
        float qp = (q0 + q1) + (q2 + q3);

        for (int jl = 0; jl < 32; jl++) {
            float u = 0.f, v = 0.f;
#pragma unroll
            for (int c = 0; c < 26; c++) {
                u += xfs[jl * 26 + c] * wa[c];
                v += xfs[jl * 26 + c] * wb[c];
            }
            g_U[((size_t)b * NOBJ + j0 + jl) * HID + h]  = u;
            g_VQ[((size_t)b * NOBJ + j0 + jl) * HID + h] = v + qp;
        }
    }
}

// ---------------- k2: fused g2->g3->g4 + pair-sum, 512 threads / 16 warps ----------------
// CTA = (b, i-pair): M=128, N=256, K=256, 3 layers. Warp tile 32(M) x 64(N): wm=warp&3, wn=warp>>2.
// A smem: [kc(4)][ks(4)][wm(4)][mt(2)][lane(32)] x 16B = 64KB. B: 2 x 32KB double-buffered.
#define B_OFF    65536u
#define WSUM_OFF 131072u
#define BIAS_OFF 135168u
#define K2_SMEM  138240u

__global__ __launch_bounds__(512, 1) void k2(const float* __restrict__ gb2,
                                             const float* __restrict__ gb3,
                                             const float* __restrict__ gb4) {
    extern __shared__ unsigned char sm[];
    unsigned char* Asm = sm;
    unsigned char* Bsm = sm + B_OFF;
    float* wsum  = (float*)(sm + WSUM_OFF);   // [16][64]
    float* biasS = (float*)(sm + BIAS_OFF);   // [3][256]
    const uint32_t sB = (uint32_t)__cvta_generic_to_shared(Bsm);

    const int tid = threadIdx.x, lane = tid & 31, warp = tid >> 5;
    const int wm = warp & 3, wn = warp >> 2;
    const int g = lane >> 2, t4 = lane & 3;
    const int b = blockIdx.x >> 5, i0 = (blockIdx.x & 31) * 2;

    if (tid < 256) { biasS[tid] = gb2[tid]; biasS[256 + tid] = gb3[tid]; biasS[512 + tid] = gb4[tid]; }

    // prefetch B chunk 0
    {
        const unsigned char* src = (const unsigned char*)g_Bh4;
#pragma unroll
        for (int t = 0; t < 4; t++) { int u = tid + t * 512; cp16(sB + u * 16, src + u * 16); }
        cp_commit();
    }

    // build layer-1 activations directly in fragment layout
    {
        const float* Ub = g_U  + (size_t)b * NOBJ * HID;
        const float* Vb = g_VQ + (size_t)b * NOBJ * HID;
        int kp = tid & 127, k0 = kp * 2;
        int kc = k0 >> 6, ks = (k0 >> 4) & 3, t4s = (k0 & 7) >> 1, pairsel = (k0 >> 3) & 1;
#pragma unroll 4
        for (int it = 0; it < 32; it++) {
            int row = it * 4 + (tid >> 7);
            float2 u = *(const float2*)(Ub + (row & 63) * HID + k0);
            float2 v = *(const float2*)(Vb + (i0 + (row >> 6)) * HID + k0);
            __half h0 = __float2half_rn(fmaxf(u.x + v.x, 0.f));
            __half h1 = __float2half_rn(fmaxf(u.y + v.y, 0.f));
            int wms = row >> 5, within = row & 31;
            int mts = (within >> 4) & 1, g8 = (within >> 3) & 1, gs = within & 7;
            int lanes = gs * 4 + t4s;
            uint32_t off = (uint32_t)(((((kc * 4 + ks) * 4 + wms) * 2 + mts) * 32 + lanes) * 16
                                      + pairsel * 8 + g8 * 4);
            *(uint32_t*)(Asm + off) = pack2(h0, h1);
        }
    }

#pragma unroll 1
    for (int l = 0; l < 3; l++) {
        float acc[2][8][4];
#pragma unroll
        for (int mt = 0; mt < 2; mt++)
#pragma unroll
            for (int nt = 0; nt < 8; nt++) {
                acc[mt][nt][0] = 0.f; acc[mt][nt][1] = 0.f; acc[mt][nt][2] = 0.f; acc[mt][nt][3] = 0.f;
            }

#pragma unroll 1
        for (int kc = 0; kc < 4; kc++) {
            const int c = l * 4 + kc;
            cp_wait0();          // chunk c resident
            __syncthreads();     // visible to all; reads of buf (c+1)&1 from iter c-1 done
            if (c < 11) {        // stream chunk c+1 into the other buffer
                const unsigned char* src = (const unsigned char*)g_Bh4 + (size_t)(c + 1) * 32768;
                uint32_t base = sB + (uint32_t)(((c + 1) & 1) * 32768);
#pragma unroll
                for (int t = 0; t < 4; t++) { int u = tid + t * 512; cp16(base + u * 16, src + u * 16); }
                cp_commit();
            }

            const unsigned char* Bb = Bsm + (c & 1) * 32768;
#pragma unroll
            for (int ks = 0; ks < 4; ks++) {
                // B fragments for this warp's 64 columns: global n-pairs wn*4 .. wn*4+3
                uint32_t bb[4][4];
                {
                    const unsigned char* Bbase = Bb +
                        (size_t)(((((wn >> 1) * 4 + ks) * 8 + (wn & 1) * 4) * 32 + lane) * 16);
#pragma unroll
                    for (int np = 0; np < 4; np++) {
                        uint4 v = *(const uint4*)(Bbase + np * 512);
                        bb[np][0] = v.x; bb[np][1] = v.y; bb[np][2] = v.z; bb[np][3] = v.w;
                    }
                }
#pragma unroll
                for (int mt = 0; mt < 2; mt++) {
                    uint4 a = *(const uint4*)(Asm + (size_t)((((((kc * 4 + ks) * 4 + wm) * 2 + mt) * 32) + lane) * 16));
#pragma unroll
                    for (int nt = 0; nt < 8; nt++) {
                        int np = nt >> 1, s = (nt & 1) * 2;
                        mma16816(acc[mt][nt], a.x, a.y, a.z, a.w, bb[np][s], bb[np][s + 1]);
                    }
                }
            }
        }
        __syncthreads();   // all mma reads of A done before epilogue overwrites A

        if (l < 2) {
            const float* bias = biasS + l * 256;
#pragma unroll
            for (int mt = 0; mt < 2; mt++)
#pragma unroll
                for (int nt = 0; nt < 8; nt++) {
                    int c0 = wn * 64 + nt * 8 + 2 * t4;
                    float bz0 = bias[c0], bz1 = bias[c0 + 1];
                    __half2 hg  = __halves2half2(__float2half_rn(fmaxf(acc[mt][nt][0] + bz0, 0.f)),
                                                 __float2half_rn(fmaxf(acc[mt][nt][1] + bz1, 0.f)));
                    __half2 hg8 = __halves2half2(__float2half_rn(fmaxf(acc[mt][nt][2] + bz0, 0.f)),
                                                 __float2half_rn(fmaxf(acc[mt][nt][3] + bz1, 0.f)));
                    int kcn = c0 >> 6, ksn = (c0 >> 4) & 3, pairsel = (c0 >> 3) & 1;
                    uint32_t off = (uint32_t)(((((kcn * 4 + ksn) * 4 + wm) * 2 + mt) * 32 + lane) * 16 + pairsel * 8);
                    uint2 st; st.x = *(uint32_t*)&hg; st.y = *(uint32_t*)&hg8;
                    *(uint2*)(Asm + off) = st;
                }
            // next-layer mma reads ordered after these writes by the sync at top of kc=0
        } else {
            const float* bias = biasS + 512;
#pragma unroll
            for (int nt = 0; nt < 8; nt++) {
                int c0 = wn * 64 + nt * 8 + 2 * t4;
                float bz0 = bias[c0], bz1 = bias[c0 + 1];
                float s0 = fmaxf(acc[0][nt][0] + bz0, 0.f) + fmaxf(acc[0][nt][2] + bz0, 0.f)
                         + fmaxf(acc[1][nt][0] + bz0, 0.f) + fmaxf(acc[1][nt][2] + bz0, 0.f);
                float s1 = fmaxf(acc[0][nt][1] + bz1, 0.f) + fmaxf(acc[0][nt][3] + bz1, 0.f)
                         + fmaxf(acc[1][nt][1] + bz1, 0.f) + fmaxf(acc[1][nt][3] + bz1, 0.f);
                s0 += __shfl_xor_sync(0xffffffffu, s0, 4);
                s0 += __shfl_xor_sync(0xffffffffu, s0, 8);
                s0 += __shfl_xor_sync(0xffffffffu, s0, 16);
                s1 += __shfl_xor_sync(0xffffffffu, s1, 4);
                s1 += __shfl_xor_sync(0xffffffffu, s1, 8);
                s1 += __shfl_xor_sync(0xffffffffu, s1, 16);
                if (g == 0) {
                    wsum[warp * 64 + nt * 8 + 2 * t4]     = s0;
                    wsum[warp * 64 + nt * 8 + 2 * t4 + 1] = s1;
                }
            }
            __syncthreads();
            if (tid < 256) {
                int wnc = tid >> 6, cl = tid & 63;
                float s = wsum[(wnc * 4 + 0) * 64 + cl] + wsum[(wnc * 4 + 1) * 64 + cl]
                        + wsum[(wnc * 4 + 2) * 64 + cl] + wsum[(wnc * 4 + 3) * 64 + cl];
                g_partial[(size_t)blockIdx.x * HID + tid] = s;
            }
        }
    }
}

// ---------------- k3: tile reduction + f-MLP + log_softmax (1024 threads, k-split) ----------------
__global__ __launch_bounds__(1024) void k3(const float* __restrict__ f1w, const float* __restrict__ f1b,
                                           const float* __restrict__ f2w, const float* __restrict__ f2b,
                                           const float* __restrict__ f3w, const float* __restrict__ f3b,
                                           float* __restrict__ out) {
    __shared__ float part[4 * 256];
    __shared__ float xg[HID], y1[HID], y2[HID];
    int b = blockIdx.x, tid = threadIdx.x;
    int col = tid & 255, q = tid >> 8;   // q in 0..3

    {
        float s = 0.f;
#pragma unroll
        for (int t = 0; t < 8; t++)
            s += g_partial[((size_t)b * 32 + q * 8 + t) * HID + col];
        part[q * 256 + col] = s;
    }
    __syncthreads();
    if (q == 0) xg[col] = (part[col] + part[256 + col]) + (part[512 + col] + part[768 + col]);
    __syncthreads();

    {
        const float* W = f1w + q * 64 * HID;
        const float* xk = xg + q * 64;
        float a0 = 0.f, a1 = 0.f, a2 = 0.f, a3 = 0.f;
#pragma unroll 8
        for (int k = 0; k < 64; k += 4) {
            a0 += xk[k]     * W[k       * HID + col];
            a1 += xk[k + 1] * W[(k + 1) * HID + col];
            a2 += xk[k + 2] * W[(k + 2) * HID + col];
            a3 += xk[k + 3] * W[(k + 3) * HID + col];
        }
        part[q * 256 + col] = (a0 + a1) + (a2 + a3);
    }
    __syncthreads();
    if (q == 0) y1[col] = fmaxf((part[col] + part[256 + col]) + (part[512 + col] + part[768 + col]) + f1b[col], 0.f);
    __syncthreads();

    {
        const float* W = f2w + q * 64 * HID;
        const float* xk = y1 + q * 64;
        float a0 = 0.f, a1 = 0.f, a2 = 0.f, a3 = 0.f;
#pragma unroll 8
        for (int k = 0; k < 64; k += 4) {
            a0 += xk[k]     * W[k       * HID + col];
            a1 += xk[k + 1] * W[(k + 1) * HID + col];
            a2 += xk[k + 2] * W[(k + 2) * HID + col];
            a3 += xk[k + 3] * W[(k + 3) * HID + col];
        }
        part[q * 256 + col] = (a0 + a1) + (a2 + a3);
    }
    __syncthreads();
    if (q == 0) y2[col] = fmaxf((part[col] + part[256 + col]) + (part[512 + col] + part[768 + col]) + f2b[col], 0.f);
    __syncthreads();

    if (tid < 256) {
        int o = tid & 31, q8 = tid >> 5;
        if (o < 28) {
            const float* W = f3w + q8 * 32 * 28;
            const float* xk = y2 + q8 * 32;
            float a0 = 0.f, a1 = 0.f;
#pragma unroll
            for (int k = 0; k < 32; k += 2) {
                a0 += xk[k]     * W[k       * 28 + o];
                a1 += xk[k + 1] * W[(k + 1) * 28 + o];
            }
            part[q8 * 28 + o] = a0 + a1;
        }
    }
    __syncthreads();

    if (tid < 32) {
        float z;
        if (tid < 28) {
            z = f3b[tid];
#pragma unroll
            for (int p = 0; p < 8; p++) z += part[p * 28 + tid];
        } else {
            z = -1e30f;
        }
        float m = z;
#pragma unroll
        for (int o = 16; o > 0; o >>= 1) m = fmaxf(m, __shfl_xor_sync(0xffffffffu, m, o));
        float e = (tid < 28) ? expf(z - m) : 0.f;
        float se = e;
#pragma unroll
        for (int o = 16; o > 0; o >>= 1) se += __shfl_xor_sync(0xffffffffu, se, o);
        if (tid < 28) out[b * 28 + tid] = z - m - logf(se);
    }
}

// ---------------- launch ----------------
extern "C" void kernel_launch(void* const* d_in, const int* in_sizes, int n_in,
                              void* d_out, int out_size) {
    (void)in_sizes; (void)n_in; (void)out_size;
    const float* x   = (const float*)d_in[0];
    const float* qst = (const float*)d_in[1];
    const float* g1w = (const float*)d_in[2];
    const float* g1b = (const float*)d_in[3];
    const float* g2w = (const float*)d_in[4];
    const float* g2b = (const float*)d_in[5];
    const float* g3w = (const float*)d_in[6];
    const float* g3b = (const float*)d_in[7];
    const float* g4w = (const float*)d_in[8];
    const float* g4b = (const float*)d_in[9];
    const float* f1w = (const float*)d_in[10];
    const float* f1b = (const float*)d_in[11];
    const float* f2w = (const float*)d_in[12];
    const float* f2b = (const float*)d_in[13];
    const float* f3w = (const float*)d_in[14];
    const float* f3b = (const float*)d_in[15];
    float* out = (float*)d_out;

    cudaFuncSetAttribute((const void*)k2, cudaFuncAttributeMaxDynamicSharedMemorySize, (int)K2_SMEM);

    k0<<<140, 256>>>(x, qst, g1w, g1b, g2w, g3w, g4w);
    k2<<<NCTA2, 512, K2_SMEM>>>(g2b, g3b, g4b);
    k3<<<64, 1024>>>(f1w, f1b, f2w, f2b, f3w, f3b, out);
}